// round 3
// baseline (speedup 1.0000x reference)
#include <cuda_runtime.h>
#include <math.h>
#include <stdint.h>

#define B_ 64
#define T_ 1024
#define D_ 256
#define H_ 512
#define O_ 256

#define GROUPS 16
#define CPG 8              // CTAs per group = cluster size (column split of H)
#define BPG (B_ / GROUPS)  // 4 batches per group
#define COLS (H_ / CPG)    // 64 output columns per CTA
#define WSTRIDE 516        // padded row stride for W slice in SMEM (conflict-free LDS.128)

// Dynamic SMEM layout (float indices)
#define MB_OFF   0                          // 2 x uint64 mbarriers (16 B)
#define W_OFF    4
#define HB_OFF   (W_OFF + COLS * WSTRIDE)   // hb[2][BPG][H_] double buffer
#define PART_OFF (HB_OFF + 2 * BPG * H_)    // part[4][BPG][COLS]
#define STG_OFF  (PART_OFF + 4 * BPG * COLS)// stg[BPG][COLS]
#define SMEM_FLOATS (STG_OFF + BPG * COLS)
#define SCAN_SMEM_BYTES (SMEM_FLOATS * 4)

// Scratch (static device allocations; runtime alloc is forbidden)
__device__ float g_xw[(size_t)B_ * T_ * H_];   // 128 MB: xW0, later reused as xW1
__device__ float g_seq[(size_t)B_ * T_ * H_];  // 128 MB: layer-0 outputs

// ---------------------------------------------------------------------------
// Packed fp32x2 helpers (exact fp32 math, 2 FMAs per instruction)
// ---------------------------------------------------------------------------
__device__ __forceinline__ unsigned long long ffma2(
    unsigned long long a, unsigned long long b, unsigned long long c) {
    unsigned long long d;
    asm("fma.rn.f32x2 %0, %1, %2, %3;" : "=l"(d) : "l"(a), "l"(b), "l"(c));
    return d;
}
__device__ __forceinline__ float2 unpk(unsigned long long a) {
    float2 f;
    asm("mov.b64 {%0, %1}, %2;" : "=f"(f.x), "=f"(f.y) : "l"(a));
    return f;
}

// ---------------------------------------------------------------------------
// Cluster / mbarrier helpers
// ---------------------------------------------------------------------------
__device__ __forceinline__ uint32_t smem_u32(const void* p) {
    return (uint32_t)__cvta_generic_to_shared(p);
}
__device__ __forceinline__ uint32_t mapa_u32(uint32_t local_addr, uint32_t rank) {
    uint32_t r;
    asm("mapa.shared::cluster.u32 %0, %1, %2;" : "=r"(r) : "r"(local_addr), "r"(rank));
    return r;
}
__device__ __forceinline__ void stc_v4(uint32_t addr, float4 v) {
    asm volatile("st.shared::cluster.v4.f32 [%0], {%1,%2,%3,%4};"
                 :: "r"(addr), "f"(v.x), "f"(v.y), "f"(v.z), "f"(v.w) : "memory");
}
#define MBAR_INIT(addr, cnt) \
    asm volatile("mbarrier.init.shared.b64 [%0], %1;" :: "r"(addr), "r"(cnt) : "memory")
#define MBAR_ARRIVE_PEER(local_addr, rank) \
    asm volatile("{\n\t.reg .b32 ra;\n\t" \
                 "mapa.shared::cluster.u32 ra, %0, %1;\n\t" \
                 "mbarrier.arrive.release.cluster.shared::cluster.b64 _, [ra];\n\t}" \
                 :: "r"(local_addr), "r"(rank) : "memory")
#define MBAR_WAIT_CLUSTER(addr, parity) do { \
    asm volatile("{\n\t.reg .pred P;\n\t" \
                 "WL_%=:\n\t" \
                 "mbarrier.try_wait.parity.acquire.cluster.shared::cta.b64 P, [%0], %1, 0x989680;\n\t" \
                 "@P bra.uni WD_%=;\n\t" \
                 "bra.uni WL_%=;\n\t" \
                 "WD_%=:\n\t}" :: "r"(addr), "r"(parity) : "memory"); \
} while (0)
#define CLUSTER_SYNC() do { \
    asm volatile("barrier.cluster.arrive.aligned;" ::: "memory"); \
    asm volatile("barrier.cluster.wait.aligned;" ::: "memory"); \
} while (0)

// ---------------------------------------------------------------------------
// tf32 tensor-core GEMM: C[M,N] = A[M,K] @ B[N,K]^T + bias1[N] + bias2[N]
// 128x128 tile, BK=32, 256 threads, warp tile 32x64 (m16n8k8). (unchanged, R2)
// ---------------------------------------------------------------------------
__device__ __forceinline__ unsigned f2tf32(float f) {
    unsigned r;
    asm("cvt.rna.tf32.f32 %0, %1;" : "=r"(r) : "f"(f));
    return r;
}
__device__ __forceinline__ void mma_tf32(float* c, unsigned a0, unsigned a1,
                                         unsigned a2, unsigned a3,
                                         unsigned b0, unsigned b1) {
    asm volatile(
        "mma.sync.aligned.m16n8k8.row.col.f32.tf32.tf32.f32 "
        "{%0,%1,%2,%3}, {%4,%5,%6,%7}, {%8,%9}, {%0,%1,%2,%3};\n"
        : "+f"(c[0]), "+f"(c[1]), "+f"(c[2]), "+f"(c[3])
        : "r"(a0), "r"(a1), "r"(a2), "r"(a3), "r"(b0), "r"(b1));
}

__global__ void __launch_bounds__(256) gemm_tf32(
    const float* __restrict__ A, const float* __restrict__ Bm,
    const float* __restrict__ b1, const float* __restrict__ b2,
    float* __restrict__ C, int M, int N, int K)
{
    __shared__ unsigned Asm[128 * 36];
    __shared__ unsigned Bsm[128 * 36];

    const int m0 = blockIdx.y * 128;
    const int n0 = blockIdx.x * 128;
    const int tid = threadIdx.x;
    const int lane = tid & 31;
    const int wid = tid >> 5;
    const int wm = wid & 3;
    const int wn = wid >> 2;
    const int l4 = lane >> 2;
    const int lm = lane & 3;

    float acc[2][8][4];
#pragma unroll
    for (int i = 0; i < 2; i++)
#pragma unroll
        for (int j = 0; j < 8; j++)
#pragma unroll
            for (int k = 0; k < 4; k++) acc[i][j][k] = 0.f;

    for (int k0 = 0; k0 < K; k0 += 32) {
#pragma unroll
        for (int i = 0; i < 4; i++) {
            int qg = tid + 256 * i;
            int row = qg >> 3;
            int q = qg & 7;
            float4 va = *(const float4*)(A + (size_t)(m0 + row) * K + k0 + q * 4);
            unsigned* da = &Asm[row * 36 + q * 4];
            da[0] = f2tf32(va.x); da[1] = f2tf32(va.y);
            da[2] = f2tf32(va.z); da[3] = f2tf32(va.w);
            float4 vb = *(const float4*)(Bm + (size_t)(n0 + row) * K + k0 + q * 4);
            unsigned* db = &Bsm[row * 36 + q * 4];
            db[0] = f2tf32(vb.x); db[1] = f2tf32(vb.y);
            db[2] = f2tf32(vb.z); db[3] = f2tf32(vb.w);
        }
        __syncthreads();

#pragma unroll
        for (int ks = 0; ks < 4; ks++) {
            unsigned a[2][4];
#pragma unroll
            for (int mt = 0; mt < 2; mt++) {
                const unsigned* ap = &Asm[(wm * 32 + mt * 16 + l4) * 36 + ks * 8 + lm];
                a[mt][0] = ap[0];
                a[mt][1] = ap[8 * 36];
                a[mt][2] = ap[4];
                a[mt][3] = ap[8 * 36 + 4];
            }
#pragma unroll
            for (int nt = 0; nt < 8; nt++) {
                const unsigned* bp = &Bsm[(wn * 64 + nt * 8 + l4) * 36 + ks * 8 + lm];
                unsigned b0 = bp[0];
                unsigned b1v = bp[4];
                mma_tf32(acc[0][nt], a[0][0], a[0][1], a[0][2], a[0][3], b0, b1v);
                mma_tf32(acc[1][nt], a[1][0], a[1][1], a[1][2], a[1][3], b0, b1v);
            }
        }
        __syncthreads();
    }

#pragma unroll
    for (int nt = 0; nt < 8; nt++) {
        int n = n0 + wn * 64 + nt * 8 + 2 * lm;
        float bv0 = b1[n] + b2[n];
        float bv1 = b1[n + 1] + b2[n + 1];
#pragma unroll
        for (int mt = 0; mt < 2; mt++) {
            int r = m0 + wm * 32 + mt * 16 + l4;
            float2 v0 = make_float2(acc[mt][nt][0] + bv0, acc[mt][nt][1] + bv1);
            float2 v1 = make_float2(acc[mt][nt][2] + bv0, acc[mt][nt][3] + bv1);
            *(float2*)(C + (size_t)r * N + n) = v0;
            *(float2*)(C + (size_t)(r + 8) * N + n) = v1;
        }
    }
}

// ---------------------------------------------------------------------------
// Cluster-based persistent recurrent scan.
// Grid = 128 CTAs = 16 clusters of 8. Cluster = one group (4 batches).
// CTA rank r owns output columns [r*64, r*64+64); W slice (64x512) in SMEM.
// h exchange: DSMEM push to all 8 peers + mbarrier arrive/wait. No global mem
// on the critical path, no threadfence, no L1 flush.
// ---------------------------------------------------------------------------
template <bool STORE_SEQ, bool FUSE_FC>
__global__ void __launch_bounds__(256) __cluster_dims__(CPG, 1, 1)
scan_kernel(const float* __restrict__ Whh,
            const float* __restrict__ Wfc, const float* __restrict__ bfc,
            float* __restrict__ out)
{
    extern __shared__ float sm[];
    float* Wt = sm + W_OFF;

    const int tid = threadIdx.x;
    const int g = blockIdx.x >> 3;
    const uint32_t rank = blockIdx.x & 7;   // == cluster_ctarank (cluster is x-major)

    const uint32_t smb = smem_u32(sm);
    const uint32_t mb0 = smb + MB_OFF * 4;
    const uint32_t mb1 = mb0 + 8;

    // Load W slice: rows rank*64 .. rank*64+63 of W_hh (coalesced LDG)
    for (int i = tid; i < COLS * H_; i += 256) {
        int r = i >> 9;
        int k = i & (H_ - 1);
        Wt[r * WSTRIDE + k] = Whh[(size_t)(rank * COLS + r) * H_ + k];
    }
    // h0 = 0 in buffer 0
    for (int i = tid; i < BPG * H_; i += 256) sm[HB_OFF + i] = 0.f;
    if (tid == 0) {
        MBAR_INIT(mb0, CPG);
        MBAR_INIT(mb1, CPG);
    }
    __syncthreads();
    CLUSTER_SYNC();   // all peers' mbarriers + buffers ready before any push

    const int c_loc = tid & 63;   // GEMM mapping: output column within slice
    const int kg    = tid >> 6;   // GEMM mapping: K-slice (4 x 128)
    const int ob    = tid >> 6;   // reduce mapping: batch
    const int oj    = tid & 63;   // reduce mapping: column
    const int bglob = g * BPG + ob;
    const int jglob = (int)rank * COLS + oj;
    const int wid   = tid >> 5;
    const int lane  = tid & 31;

    const float* xwp = g_xw + (size_t)bglob * T_ * H_ + jglob;
    // W row for this thread's column, as packed k-pairs (ulonglong2 = 4 k's)
    const ulonglong2* w2 = (const ulonglong2*)(Wt + c_loc * WSTRIDE + kg * 128);

    unsigned par0 = 0, par1 = 0;

    for (int t = 0; t < T_; t++) {
        // stream this step's input projection early (hides under wait + GEMM)
        float xw_r = __ldcg(xwp + (size_t)t * H_);

        const int p = t & 1;
        if (t > 0) {
            if (p == 0) { MBAR_WAIT_CLUSTER(mb0, par0); par0 ^= 1; }
            else        { MBAR_WAIT_CLUSTER(mb1, par1); par1 ^= 1; }
        }

        const float* hbp = sm + HB_OFF + p * (BPG * H_);
        const ulonglong2* h0 = (const ulonglong2*)(hbp + 0 * H_ + kg * 128);
        const ulonglong2* h1 = (const ulonglong2*)(hbp + 1 * H_ + kg * 128);
        const ulonglong2* h2 = (const ulonglong2*)(hbp + 2 * H_ + kg * 128);
        const ulonglong2* h3 = (const ulonglong2*)(hbp + 3 * H_ + kg * 128);

        // packed fp32x2 GEMM over this thread's 128-k slice, 4 batches
        unsigned long long a0 = 0ull, a1 = 0ull, a2 = 0ull, a3 = 0ull;
#pragma unroll
        for (int q = 0; q < 32; q++) {
            ulonglong2 w = w2[q];      // k-pairs (4q,4q+1), (4q+2,4q+3)
            ulonglong2 v0 = h0[q];     // broadcast LDS
            a0 = ffma2(w.x, v0.x, a0);
            a0 = ffma2(w.y, v0.y, a0);
            ulonglong2 v1 = h1[q];
            a1 = ffma2(w.x, v1.x, a1);
            a1 = ffma2(w.y, v1.y, a1);
            ulonglong2 v2 = h2[q];
            a2 = ffma2(w.x, v2.x, a2);
            a2 = ffma2(w.y, v2.y, a2);
            ulonglong2 v3 = h3[q];
            a3 = ffma2(w.x, v3.x, a3);
            a3 = ffma2(w.y, v3.y, a3);
        }
        float2 u0 = unpk(a0), u1 = unpk(a1), u2 = unpk(a2), u3 = unpk(a3);
        // part[kg][b][col]
        sm[PART_OFF + kg * (BPG * COLS) + 0 * COLS + c_loc] = u0.x + u0.y;
        sm[PART_OFF + kg * (BPG * COLS) + 1 * COLS + c_loc] = u1.x + u1.y;
        sm[PART_OFF + kg * (BPG * COLS) + 2 * COLS + c_loc] = u2.x + u2.y;
        sm[PART_OFF + kg * (BPG * COLS) + 3 * COLS + c_loc] = u3.x + u3.y;
        __syncthreads();

        float s = sm[PART_OFF + 0 * (BPG * COLS) + ob * COLS + oj]
                + sm[PART_OFF + 1 * (BPG * COLS) + ob * COLS + oj]
                + sm[PART_OFF + 2 * (BPG * COLS) + ob * COLS + oj]
                + sm[PART_OFF + 3 * (BPG * COLS) + ob * COLS + oj]
                + xw_r;
        float hn = tanhf(s);

        if (STORE_SEQ) __stcg(&g_seq[((size_t)bglob * T_ + t) * H_ + jglob], hn);

        const int qb = p ^ 1;
        if ((t + 1 < T_) || FUSE_FC) {
            sm[STG_OFF + ob * COLS + oj] = hn;   // stage own chunk [b][col]
            __syncthreads();
            // warp w pushes the chunk to peer w's hb[qb] (4 row segments)
            const uint32_t dst_base = smb + (HB_OFF + qb * (BPG * H_)) * 4u;
#pragma unroll
            for (int r2 = 0; r2 < 2; r2++) {
                int f = lane + 32 * r2;           // 0..63 float4 of the chunk
                int b = f >> 4;
                int c4 = f & 15;
                float4 v = *(const float4*)(sm + STG_OFF + b * COLS + c4 * 4);
                uint32_t daddr = dst_base + (uint32_t)(b * H_ + (int)rank * COLS + c4 * 4) * 4u;
                stc_v4(mapa_u32(daddr, (uint32_t)wid), v);
            }
            __syncthreads();   // all pushes issued before arrives (cumulativity)
            if (tid < CPG) {
                MBAR_ARRIVE_PEER((qb == 0) ? mb0 : mb1, (uint32_t)tid);
            }
        } else {
            __syncthreads();
        }
    }

    if (FUSE_FC) {
        // last push landed in hb[0]; wait for it then compute fc from SMEM
        MBAR_WAIT_CLUSTER(mb0, par0);
        if (tid < 128) {
            int b = tid >> 5;
            int nl = tid & 31;
            int n = (int)rank * (O_ / CPG) + nl;
            const float4* hT = (const float4*)(sm + HB_OFF + b * H_);
            const float4* wf = (const float4*)(Wfc + (size_t)n * H_);
            float acc = 0.f;
#pragma unroll 8
            for (int k4 = 0; k4 < H_ / 4; k4++) {
                float4 a = wf[k4];
                float4 x = hT[k4];
                acc += a.x * x.x + a.y * x.y + a.z * x.z + a.w * x.w;
            }
            out[(g * BPG + b) * O_ + n] = acc + bfc[n];
        }
    }
    CLUSTER_SYNC();   // no CTA exits while peers may still touch its SMEM
}

// ---------------------------------------------------------------------------

extern "C" void kernel_launch(void* const* d_in, const int* in_sizes, int n_in,
                              void* d_out, int out_size)
{
    const float* x     = (const float*)d_in[0];
    const float* W_ih0 = (const float*)d_in[1];
    const float* W_hh0 = (const float*)d_in[2];
    const float* b_ih0 = (const float*)d_in[3];
    const float* b_hh0 = (const float*)d_in[4];
    const float* W_ih1 = (const float*)d_in[5];
    const float* W_hh1 = (const float*)d_in[6];
    const float* b_ih1 = (const float*)d_in[7];
    const float* b_hh1 = (const float*)d_in[8];
    const float* W_fc  = (const float*)d_in[9];
    const float* b_fc  = (const float*)d_in[10];
    float* out = (float*)d_out;

    void* p_xw = nullptr;
    void* p_seq = nullptr;
    cudaGetSymbolAddress(&p_xw, g_xw);
    cudaGetSymbolAddress(&p_seq, g_seq);

    cudaFuncSetAttribute(scan_kernel<true, false>,
                         cudaFuncAttributeMaxDynamicSharedMemorySize, SCAN_SMEM_BYTES);
    cudaFuncSetAttribute(scan_kernel<false, true>,
                         cudaFuncAttributeMaxDynamicSharedMemorySize, SCAN_SMEM_BYTES);

    const int MT = B_ * T_;  // 65536

    // Layer 0 input projection: g_xw = x @ W_ih0^T + b_ih0 + b_hh0
    gemm_tf32<<<dim3(H_ / 128, MT / 128), 256>>>(
        x, W_ih0, b_ih0, b_hh0, (float*)p_xw, MT, H_, D_);

    // Layer 0 scan -> g_seq
    scan_kernel<true, false><<<GROUPS * CPG, 256, SCAN_SMEM_BYTES>>>(
        W_hh0, nullptr, nullptr, nullptr);

    // Layer 1 input projection: g_xw = g_seq @ W_ih1^T + b_ih1 + b_hh1
    gemm_tf32<<<dim3(H_ / 128, MT / 128), 256>>>(
        (const float*)p_seq, W_ih1, b_ih1, b_hh1, (float*)p_xw, MT, H_, H_);

    // Layer 1 scan + fused fc -> out
    scan_kernel<false, true><<<GROUPS * CPG, 256, SCAN_SMEM_BYTES>>>(
        W_hh1, W_fc, b_fc, out);
}

// round 5
// speedup vs baseline: 1.2367x; 1.2367x over previous
#include <cuda_runtime.h>
#include <math.h>
#include <stdint.h>

#define B_ 64
#define T_ 1024
#define D_ 256
#define H_ 512
#define O_ 256

#define GROUPS 16
#define CPG 8              // CTAs per group (column split of H)
#define BPG (B_ / GROUPS)  // 4 batches per group
#define COLS (H_ / CPG)    // 64 output columns per CTA

typedef unsigned long long ull;

// Scratch (static device allocations; runtime alloc is forbidden)
__device__ float    g_xw[(size_t)B_ * T_ * H_];   // 128 MB: xW0, later reused as xW1
__device__ float    g_seq[(size_t)B_ * T_ * H_];  // 128 MB: layer-0 outputs
__device__ float    g_h[2][B_][H_];               // double-buffered hidden exchange
// Self-resetting barrier: cnt returns to 0 each step; phase flips 1024x per scan
// (even per launch) -> state identical across graph replays, no init kernel.
__device__ unsigned g_cnt[GROUPS];
__device__ unsigned g_phase[GROUPS];

// ---------------------------------------------------------------------------
// Packed fp32x2 helpers (exact fp32 math, 2 FMAs per instruction)
// ---------------------------------------------------------------------------
__device__ __forceinline__ ull ffma2(ull a, ull b, ull c) {
    ull d;
    asm("fma.rn.f32x2 %0, %1, %2, %3;" : "=l"(d) : "l"(a), "l"(b), "l"(c));
    return d;
}
__device__ __forceinline__ ull addf2(ull a, ull b) {
    ull d;
    asm("add.rn.f32x2 %0, %1, %2;" : "=l"(d) : "l"(a), "l"(b));
    return d;
}
__device__ __forceinline__ ull pk2(float x, float y) {
    ull r;
    asm("mov.b64 %0, {%1, %2};" : "=l"(r) : "f"(x), "f"(y));
    return r;
}
__device__ __forceinline__ float2 unpk(ull a) {
    float2 f;
    asm("mov.b64 {%0, %1}, %2;" : "=f"(f.x), "=f"(f.y) : "l"(a));
    return f;
}

// ---------------------------------------------------------------------------
// tf32 tensor-core GEMM: C[M,N] = A[M,K] @ B[N,K]^T + bias1[N] + bias2[N]
// 128x128 tile, BK=32, 256 threads, warp tile 32x64 (m16n8k8). (unchanged, R2)
// ---------------------------------------------------------------------------
__device__ __forceinline__ unsigned f2tf32(float f) {
    unsigned r;
    asm("cvt.rna.tf32.f32 %0, %1;" : "=r"(r) : "f"(f));
    return r;
}
__device__ __forceinline__ void mma_tf32(float* c, unsigned a0, unsigned a1,
                                         unsigned a2, unsigned a3,
                                         unsigned b0, unsigned b1) {
    asm volatile(
        "mma.sync.aligned.m16n8k8.row.col.f32.tf32.tf32.f32 "
        "{%0,%1,%2,%3}, {%4,%5,%6,%7}, {%8,%9}, {%0,%1,%2,%3};\n"
        : "+f"(c[0]), "+f"(c[1]), "+f"(c[2]), "+f"(c[3])
        : "r"(a0), "r"(a1), "r"(a2), "r"(a3), "r"(b0), "r"(b1));
}

__global__ void __launch_bounds__(256) gemm_tf32(
    const float* __restrict__ A, const float* __restrict__ Bm,
    const float* __restrict__ b1, const float* __restrict__ b2,
    float* __restrict__ C, int M, int N, int K)
{
    __shared__ unsigned Asm[128 * 36];
    __shared__ unsigned Bsm[128 * 36];

    const int m0 = blockIdx.y * 128;
    const int n0 = blockIdx.x * 128;
    const int tid = threadIdx.x;
    const int lane = tid & 31;
    const int wid = tid >> 5;
    const int wm = wid & 3;
    const int wn = wid >> 2;
    const int l4 = lane >> 2;
    const int lm = lane & 3;

    float acc[2][8][4];
#pragma unroll
    for (int i = 0; i < 2; i++)
#pragma unroll
        for (int j = 0; j < 8; j++)
#pragma unroll
            for (int k = 0; k < 4; k++) acc[i][j][k] = 0.f;

    for (int k0 = 0; k0 < K; k0 += 32) {
#pragma unroll
        for (int i = 0; i < 4; i++) {
            int qg = tid + 256 * i;
            int row = qg >> 3;
            int q = qg & 7;
            float4 va = *(const float4*)(A + (size_t)(m0 + row) * K + k0 + q * 4);
            unsigned* da = &Asm[row * 36 + q * 4];
            da[0] = f2tf32(va.x); da[1] = f2tf32(va.y);
            da[2] = f2tf32(va.z); da[3] = f2tf32(va.w);
            float4 vb = *(const float4*)(Bm + (size_t)(n0 + row) * K + k0 + q * 4);
            unsigned* db = &Bsm[row * 36 + q * 4];
            db[0] = f2tf32(vb.x); db[1] = f2tf32(vb.y);
            db[2] = f2tf32(vb.z); db[3] = f2tf32(vb.w);
        }
        __syncthreads();

#pragma unroll
        for (int ks = 0; ks < 4; ks++) {
            unsigned a[2][4];
#pragma unroll
            for (int mt = 0; mt < 2; mt++) {
                const unsigned* ap = &Asm[(wm * 32 + mt * 16 + l4) * 36 + ks * 8 + lm];
                a[mt][0] = ap[0];
                a[mt][1] = ap[8 * 36];
                a[mt][2] = ap[4];
                a[mt][3] = ap[8 * 36 + 4];
            }
#pragma unroll
            for (int nt = 0; nt < 8; nt++) {
                const unsigned* bp = &Bsm[(wn * 64 + nt * 8 + l4) * 36 + ks * 8 + lm];
                unsigned b0 = bp[0];
                unsigned b1v = bp[4];
                mma_tf32(acc[0][nt], a[0][0], a[0][1], a[0][2], a[0][3], b0, b1v);
                mma_tf32(acc[1][nt], a[1][0], a[1][1], a[1][2], a[1][3], b0, b1v);
            }
        }
        __syncthreads();
    }

#pragma unroll
    for (int nt = 0; nt < 8; nt++) {
        int n = n0 + wn * 64 + nt * 8 + 2 * lm;
        float bv0 = b1[n] + b2[n];
        float bv1 = b1[n + 1] + b2[n + 1];
#pragma unroll
        for (int mt = 0; mt < 2; mt++) {
            int r = m0 + wm * 32 + mt * 16 + l4;
            float2 v0 = make_float2(acc[mt][nt][0] + bv0, acc[mt][nt][1] + bv1);
            float2 v1 = make_float2(acc[mt][nt][2] + bv0, acc[mt][nt][3] + bv1);
            *(float2*)(C + (size_t)r * N + n) = v0;
            *(float2*)(C + (size_t)(r + 8) * N + n) = v1;
        }
    }
}

// ---------------------------------------------------------------------------
// Persistent recurrent scan, W-in-registers edition.
// Grid = 128 CTAs (classic launch, all wave-1 resident). CTA (g,c): batches
// [g*4, g*4+4), output columns [c*64, c*64+64).
// Thread (kg = tid>>6, c_loc = tid&63) holds W[c*64+c_loc][kg*128 .. +128) in
// 64 packed b64 registers. Per step: h (broadcast LDS) x W (regs) via FFMA2,
// cross-thread k-reduce through part[], exchange via g_h in L2 with a
// release/acquire sense-reversal barrier (no threadfence, no L1 flush).
// ---------------------------------------------------------------------------
template <bool STORE_SEQ, bool FUSE_FC>
__global__ void __launch_bounds__(256) scan_kernel(
    const float* __restrict__ Whh,
    const float* __restrict__ Wfc, const float* __restrict__ bfc,
    float* __restrict__ out)
{
    __shared__ __align__(16) float hb[BPG][H_];        // 8 KB: group hidden state
    __shared__ __align__(16) float part[4][BPG][COLS]; // 4 KB: k-partials

    const int tid = threadIdx.x;
    const int g = blockIdx.x >> 3;
    const int c = blockIdx.x & 7;

    const int c_loc = tid & 63;   // output column within slice
    const int kg    = tid >> 6;   // K-slice (4 x 128)
    const int ob    = tid >> 6;   // reduce mapping: batch
    const int oj    = tid & 63;   // reduce mapping: column
    const int bglob = g * BPG + ob;
    const int jglob = c * COLS + oj;

    // ---- W slice into registers (one-time; 16 CTAs share each slice via L2)
    ull w[64];
    {
        const float4* wp = (const float4*)(Whh + (size_t)(c * COLS + c_loc) * H_ + kg * 128);
#pragma unroll
        for (int i = 0; i < 32; i++) {
            float4 v = wp[i];
            w[2 * i]     = pk2(v.x, v.y);
            w[2 * i + 1] = pk2(v.z, v.w);
        }
    }

    for (int i = tid; i < BPG * H_; i += 256) (&hb[0][0])[i] = 0.f;  // h0 = 0
    __syncthreads();

    const float* xwp = g_xw + (size_t)bglob * T_ * H_ + jglob;
    unsigned phase = 0;

    for (int t = 0; t < T_; t++) {
        // stream this step's input projection early (hides L2 latency)
        float xw_r = __ldcg(xwp + (size_t)t * H_);

        const ulonglong2* h0 = (const ulonglong2*)&hb[0][kg * 128];
        const ulonglong2* h1 = (const ulonglong2*)&hb[1][kg * 128];
        const ulonglong2* h2 = (const ulonglong2*)&hb[2][kg * 128];
        const ulonglong2* h3 = (const ulonglong2*)&hb[3][kg * 128];

        ull a0 = 0ull, b0 = 0ull, a1 = 0ull, b1 = 0ull;
        ull a2 = 0ull, b2 = 0ull, a3 = 0ull, b3 = 0ull;
#pragma unroll
        for (int q = 0; q < 32; q++) {
            ulonglong2 v0 = h0[q];   // broadcast LDS.128 (all lanes same addr)
            a0 = ffma2(w[2 * q], v0.x, a0);
            b0 = ffma2(w[2 * q + 1], v0.y, b0);
            ulonglong2 v1 = h1[q];
            a1 = ffma2(w[2 * q], v1.x, a1);
            b1 = ffma2(w[2 * q + 1], v1.y, b1);
            ulonglong2 v2 = h2[q];
            a2 = ffma2(w[2 * q], v2.x, a2);
            b2 = ffma2(w[2 * q + 1], v2.y, b2);
            ulonglong2 v3 = h3[q];
            a3 = ffma2(w[2 * q], v3.x, a3);
            b3 = ffma2(w[2 * q + 1], v3.y, b3);
        }
        float2 s0 = unpk(addf2(a0, b0));
        float2 s1 = unpk(addf2(a1, b1));
        float2 s2 = unpk(addf2(a2, b2));
        float2 s3 = unpk(addf2(a3, b3));
        part[kg][0][c_loc] = s0.x + s0.y;
        part[kg][1][c_loc] = s1.x + s1.y;
        part[kg][2][c_loc] = s2.x + s2.y;
        part[kg][3][c_loc] = s3.x + s3.y;
        __syncthreads();

        float s = part[0][ob][oj] + part[1][ob][oj] + part[2][ob][oj]
                + part[3][ob][oj] + xw_r;
        float hn = tanhf(s);

        const int p = t & 1;
        __stcg(&g_h[p][bglob][jglob], hn);
        if (STORE_SEQ) __stcg(&g_seq[((size_t)bglob * T_ + t) * H_ + jglob], hn);

        // ---- group barrier: release-arrive / acquire-poll (no membar.gpu)
        __syncthreads();  // all stcg above happen-before tid0's release atom
        unsigned want = phase ^ 1u;
        if (tid == 0) {
            unsigned old;
            asm volatile("atom.release.gpu.global.add.u32 %0, [%1], %2;"
                         : "=r"(old) : "l"(&g_cnt[g]), "r"(1u) : "memory");
            if (old == CPG - 1) {
                asm volatile("st.relaxed.gpu.global.u32 [%0], %1;"
                             :: "l"(&g_cnt[g]), "r"(0u) : "memory");
                asm volatile("st.release.gpu.global.u32 [%0], %1;"
                             :: "l"(&g_phase[g]), "r"(want) : "memory");
            } else {
                unsigned cur;
                do {
                    asm volatile("ld.acquire.gpu.global.u32 %0, [%1];"
                                 : "=r"(cur) : "l"(&g_phase[g]) : "memory");
                } while (cur != want);
            }
        }
        __syncthreads();
        phase = want;

        // reload full group hidden state (8 KB from L2)
        const float4* src = (const float4*)&g_h[p][g * BPG][0];
        float4* dst = (float4*)&hb[0][0];
        dst[tid] = __ldcg(src + tid);
        dst[tid + 256] = __ldcg(src + tid + 256);
        __syncthreads();
    }

    if (FUSE_FC) {
        // hb now holds h_T for the group's 4 batches (full H).
        if (tid < 128) {
            int b = tid >> 5;
            int nl = tid & 31;
            int n = c * (O_ / CPG) + nl;
            const float4* hT = (const float4*)&hb[b][0];
            const float4* wf = (const float4*)(Wfc + (size_t)n * H_);
            float acc = 0.f;
#pragma unroll 8
            for (int k4 = 0; k4 < H_ / 4; k4++) {
                float4 a = wf[k4];
                float4 x = hT[k4];
                acc += a.x * x.x + a.y * x.y + a.z * x.z + a.w * x.w;
            }
            out[(g * BPG + b) * O_ + n] = acc + bfc[n];
        }
    }
}

// ---------------------------------------------------------------------------

extern "C" void kernel_launch(void* const* d_in, const int* in_sizes, int n_in,
                              void* d_out, int out_size)
{
    const float* x     = (const float*)d_in[0];
    const float* W_ih0 = (const float*)d_in[1];
    const float* W_hh0 = (const float*)d_in[2];
    const float* b_ih0 = (const float*)d_in[3];
    const float* b_hh0 = (const float*)d_in[4];
    const float* W_ih1 = (const float*)d_in[5];
    const float* W_hh1 = (const float*)d_in[6];
    const float* b_ih1 = (const float*)d_in[7];
    const float* b_hh1 = (const float*)d_in[8];
    const float* W_fc  = (const float*)d_in[9];
    const float* b_fc  = (const float*)d_in[10];
    float* out = (float*)d_out;

    void* p_xw = nullptr;
    void* p_seq = nullptr;
    cudaGetSymbolAddress(&p_xw, g_xw);
    cudaGetSymbolAddress(&p_seq, g_seq);

    const int MT = B_ * T_;  // 65536

    // Layer 0 input projection: g_xw = x @ W_ih0^T + b_ih0 + b_hh0
    gemm_tf32<<<dim3(H_ / 128, MT / 128), 256>>>(
        x, W_ih0, b_ih0, b_hh0, (float*)p_xw, MT, H_, D_);

    // Layer 0 scan -> g_seq
    scan_kernel<true, false><<<GROUPS * CPG, 256>>>(
        W_hh0, nullptr, nullptr, nullptr);

    // Layer 1 input projection: g_xw = g_seq @ W_ih1^T + b_ih1 + b_hh1
    gemm_tf32<<<dim3(H_ / 128, MT / 128), 256>>>(
        (const float*)p_seq, W_ih1, b_ih1, b_hh1, (float*)p_xw, MT, H_, H_);

    // Layer 1 scan + fused fc -> out
    scan_kernel<false, true><<<GROUPS * CPG, 256>>>(
        W_hh1, W_fc, b_fc, out);
}

// round 6
// speedup vs baseline: 1.4698x; 1.1885x over previous
#include <cuda_runtime.h>
#include <math.h>
#include <stdint.h>

#define B_ 64
#define T_ 1024
#define D_ 256
#define H_ 512
#define O_ 256

#define GROUPS 16
#define CPG 8              // CTAs per group (column split of H)
#define BPG (B_ / GROUPS)  // 4 batches per group
#define COLS (H_ / CPG)    // 64 output columns per CTA

typedef unsigned long long ull;

// Scratch (static device allocations; runtime alloc is forbidden)
__device__ float    g_xw[(size_t)B_ * T_ * H_];   // 128 MB: xW0, later reused as xW1
__device__ float    g_seq[(size_t)B_ * T_ * H_];  // 128 MB: layer-0 outputs
__device__ float    g_h[2][B_][H_];               // double-buffered hidden exchange
// Per-CTA arrival flags: ONE 128-byte L2 line per CTA (no atomic serialization,
// no cross-group line sharing). Values are monotonic sequence numbers:
// each scan adds exactly T_ to every slot, so all slots stay uniform across
// launches/replays; each CTA reads its own slot at start to get the base.
__device__ unsigned g_flag[GROUPS * CPG * 32];

// ---------------------------------------------------------------------------
// Packed fp32x2 helpers (exact fp32 math, 2 FMAs per instruction)
// ---------------------------------------------------------------------------
__device__ __forceinline__ ull ffma2(ull a, ull b, ull c) {
    ull d;
    asm("fma.rn.f32x2 %0, %1, %2, %3;" : "=l"(d) : "l"(a), "l"(b), "l"(c));
    return d;
}
__device__ __forceinline__ ull addf2(ull a, ull b) {
    ull d;
    asm("add.rn.f32x2 %0, %1, %2;" : "=l"(d) : "l"(a), "l"(b));
    return d;
}
__device__ __forceinline__ ull pk2(float x, float y) {
    ull r;
    asm("mov.b64 %0, {%1, %2};" : "=l"(r) : "f"(x), "f"(y));
    return r;
}
__device__ __forceinline__ float2 unpk(ull a) {
    float2 f;
    asm("mov.b64 {%0, %1}, %2;" : "=f"(f.x), "=f"(f.y) : "l"(a));
    return f;
}

// ---------------------------------------------------------------------------
// tf32 tensor-core GEMM: C[M,N] = A[M,K] @ B[N,K]^T + bias1[N] + bias2[N]
// 128x128 tile, BK=32, 256 threads, warp tile 32x64 (m16n8k8). (unchanged)
// ---------------------------------------------------------------------------
__device__ __forceinline__ unsigned f2tf32(float f) {
    unsigned r;
    asm("cvt.rna.tf32.f32 %0, %1;" : "=r"(r) : "f"(f));
    return r;
}
__device__ __forceinline__ void mma_tf32(float* c, unsigned a0, unsigned a1,
                                         unsigned a2, unsigned a3,
                                         unsigned b0, unsigned b1) {
    asm volatile(
        "mma.sync.aligned.m16n8k8.row.col.f32.tf32.tf32.f32 "
        "{%0,%1,%2,%3}, {%4,%5,%6,%7}, {%8,%9}, {%0,%1,%2,%3};\n"
        : "+f"(c[0]), "+f"(c[1]), "+f"(c[2]), "+f"(c[3])
        : "r"(a0), "r"(a1), "r"(a2), "r"(a3), "r"(b0), "r"(b1));
}

__global__ void __launch_bounds__(256) gemm_tf32(
    const float* __restrict__ A, const float* __restrict__ Bm,
    const float* __restrict__ b1, const float* __restrict__ b2,
    float* __restrict__ C, int M, int N, int K)
{
    __shared__ unsigned Asm[128 * 36];
    __shared__ unsigned Bsm[128 * 36];

    const int m0 = blockIdx.y * 128;
    const int n0 = blockIdx.x * 128;
    const int tid = threadIdx.x;
    const int lane = tid & 31;
    const int wid = tid >> 5;
    const int wm = wid & 3;
    const int wn = wid >> 2;
    const int l4 = lane >> 2;
    const int lm = lane & 3;

    float acc[2][8][4];
#pragma unroll
    for (int i = 0; i < 2; i++)
#pragma unroll
        for (int j = 0; j < 8; j++)
#pragma unroll
            for (int k = 0; k < 4; k++) acc[i][j][k] = 0.f;

    for (int k0 = 0; k0 < K; k0 += 32) {
#pragma unroll
        for (int i = 0; i < 4; i++) {
            int qg = tid + 256 * i;
            int row = qg >> 3;
            int q = qg & 7;
            float4 va = *(const float4*)(A + (size_t)(m0 + row) * K + k0 + q * 4);
            unsigned* da = &Asm[row * 36 + q * 4];
            da[0] = f2tf32(va.x); da[1] = f2tf32(va.y);
            da[2] = f2tf32(va.z); da[3] = f2tf32(va.w);
            float4 vb = *(const float4*)(Bm + (size_t)(n0 + row) * K + k0 + q * 4);
            unsigned* db = &Bsm[row * 36 + q * 4];
            db[0] = f2tf32(vb.x); db[1] = f2tf32(vb.y);
            db[2] = f2tf32(vb.z); db[3] = f2tf32(vb.w);
        }
        __syncthreads();

#pragma unroll
        for (int ks = 0; ks < 4; ks++) {
            unsigned a[2][4];
#pragma unroll
            for (int mt = 0; mt < 2; mt++) {
                const unsigned* ap = &Asm[(wm * 32 + mt * 16 + l4) * 36 + ks * 8 + lm];
                a[mt][0] = ap[0];
                a[mt][1] = ap[8 * 36];
                a[mt][2] = ap[4];
                a[mt][3] = ap[8 * 36 + 4];
            }
#pragma unroll
            for (int nt = 0; nt < 8; nt++) {
                const unsigned* bp = &Bsm[(wn * 64 + nt * 8 + l4) * 36 + ks * 8 + lm];
                unsigned b0 = bp[0];
                unsigned b1v = bp[4];
                mma_tf32(acc[0][nt], a[0][0], a[0][1], a[0][2], a[0][3], b0, b1v);
                mma_tf32(acc[1][nt], a[1][0], a[1][1], a[1][2], a[1][3], b0, b1v);
            }
        }
        __syncthreads();
    }

#pragma unroll
    for (int nt = 0; nt < 8; nt++) {
        int n = n0 + wn * 64 + nt * 8 + 2 * lm;
        float bv0 = b1[n] + b2[n];
        float bv1 = b1[n + 1] + b2[n + 1];
#pragma unroll
        for (int mt = 0; mt < 2; mt++) {
            int r = m0 + wm * 32 + mt * 16 + l4;
            float2 v0 = make_float2(acc[mt][nt][0] + bv0, acc[mt][nt][1] + bv1);
            float2 v1 = make_float2(acc[mt][nt][2] + bv0, acc[mt][nt][3] + bv1);
            *(float2*)(C + (size_t)r * N + n) = v0;
            *(float2*)(C + (size_t)(r + 8) * N + n) = v1;
        }
    }
}

// ---------------------------------------------------------------------------
// Persistent recurrent scan: W in registers, flag-based group barrier.
// Grid = 128 CTAs (1/SM, wave-1). CTA (g,c): batches [g*4,g*4+4),
// columns [c*64,c*64+64). Barrier per step: tid0 st.release own padded flag
// line = base+t+1; threads tid<8 poll the 8 peer lines in parallel (MLP=8,
// no atomics, no shared lines).
// ---------------------------------------------------------------------------
template <bool STORE_SEQ, bool FUSE_FC>
__global__ void __launch_bounds__(256) scan_kernel(
    const float* __restrict__ Whh,
    const float* __restrict__ Wfc, const float* __restrict__ bfc,
    float* __restrict__ out)
{
    __shared__ __align__(16) float hb[BPG][H_];        // 8 KB: group hidden state
    __shared__ __align__(16) float part[4][BPG][COLS]; // 4 KB: k-partials
    __shared__ unsigned sv0;                           // flag base for this launch

    const int tid = threadIdx.x;
    const int g = blockIdx.x >> 3;
    const int c = blockIdx.x & 7;

    const int c_loc = tid & 63;   // output column within slice
    const int kg    = tid >> 6;   // K-slice (4 x 128)
    const int ob    = tid >> 6;   // reduce mapping: batch
    const int oj    = tid & 63;   // reduce mapping: column
    const int bglob = g * BPG + ob;
    const int jglob = c * COLS + oj;

    // ---- W slice into registers (one-time; 16 CTAs share each slice via L2)
    ull w[64];
    {
        const float4* wp = (const float4*)(Whh + (size_t)(c * COLS + c_loc) * H_ + kg * 128);
#pragma unroll
        for (int i = 0; i < 32; i++) {
            float4 v = wp[i];
            w[2 * i]     = pk2(v.x, v.y);
            w[2 * i + 1] = pk2(v.z, v.w);
        }
    }

    // flag base: all slots are uniform between launches (each scan adds T_ to
    // every slot), so reading our own slot gives the group-wide base.
    if (tid == 0) sv0 = g_flag[(g * CPG + c) * 32];
    for (int i = tid; i < BPG * H_; i += 256) (&hb[0][0])[i] = 0.f;  // h0 = 0
    __syncthreads();
    const unsigned v0 = sv0;

    unsigned* myflag = &g_flag[(g * CPG + c) * 32];
    unsigned* peerflag = (tid < CPG) ? &g_flag[(g * CPG + tid) * 32] : nullptr;

    const float* xwp = g_xw + (size_t)bglob * T_ * H_ + jglob;

    for (int t = 0; t < T_; t++) {
        // stream this step's input projection early (hides DRAM latency)
        float xw_r = __ldcg(xwp + (size_t)t * H_);

        const ulonglong2* h0 = (const ulonglong2*)&hb[0][kg * 128];
        const ulonglong2* h1 = (const ulonglong2*)&hb[1][kg * 128];
        const ulonglong2* h2 = (const ulonglong2*)&hb[2][kg * 128];
        const ulonglong2* h3 = (const ulonglong2*)&hb[3][kg * 128];

        ull a0 = 0ull, b0 = 0ull, a1 = 0ull, b1 = 0ull;
        ull a2 = 0ull, b2 = 0ull, a3 = 0ull, b3 = 0ull;
#pragma unroll
        for (int q = 0; q < 32; q++) {
            ulonglong2 v0v = h0[q];   // broadcast LDS.128
            a0 = ffma2(w[2 * q], v0v.x, a0);
            b0 = ffma2(w[2 * q + 1], v0v.y, b0);
            ulonglong2 v1 = h1[q];
            a1 = ffma2(w[2 * q], v1.x, a1);
            b1 = ffma2(w[2 * q + 1], v1.y, b1);
            ulonglong2 v2 = h2[q];
            a2 = ffma2(w[2 * q], v2.x, a2);
            b2 = ffma2(w[2 * q + 1], v2.y, b2);
            ulonglong2 v3 = h3[q];
            a3 = ffma2(w[2 * q], v3.x, a3);
            b3 = ffma2(w[2 * q + 1], v3.y, b3);
        }
        float2 s0 = unpk(addf2(a0, b0));
        float2 s1 = unpk(addf2(a1, b1));
        float2 s2 = unpk(addf2(a2, b2));
        float2 s3 = unpk(addf2(a3, b3));
        part[kg][0][c_loc] = s0.x + s0.y;
        part[kg][1][c_loc] = s1.x + s1.y;
        part[kg][2][c_loc] = s2.x + s2.y;
        part[kg][3][c_loc] = s3.x + s3.y;
        __syncthreads();

        float s = part[0][ob][oj] + part[1][ob][oj] + part[2][ob][oj]
                + part[3][ob][oj] + xw_r;
        float hn = tanhf(s);

        const int p = t & 1;
        if (STORE_SEQ) __stcg(&g_seq[((size_t)bglob * T_ + t) * H_ + jglob], hn);

        if ((t + 1 < T_) || FUSE_FC) {
            __stcg(&g_h[p][bglob][jglob], hn);

            // ---- flag barrier: release own line, poll 8 peer lines in parallel
            __syncthreads();   // all stcg above precede tid0's release store
            const unsigned want = v0 + (unsigned)t + 1u;
            if (tid == 0) {
                asm volatile("st.release.gpu.global.u32 [%0], %1;"
                             :: "l"(myflag), "r"(want) : "memory");
            }
            if (tid < CPG) {
                unsigned cur;
                do {
                    asm volatile("ld.acquire.gpu.global.u32 %0, [%1];"
                                 : "=r"(cur) : "l"(peerflag) : "memory");
                } while ((int)(cur - want) < 0);
            }
            __syncthreads();

            // reload full group hidden state (8 KB from L2)
            const float4* src = (const float4*)&g_h[p][g * BPG][0];
            float4* dst = (float4*)&hb[0][0];
            dst[tid] = __ldcg(src + tid);
            dst[tid + 256] = __ldcg(src + tid + 256);
            __syncthreads();
        } else {
            __syncthreads();   // keep flag slots uniform: bump even on last step
            if (tid == 0) {
                asm volatile("st.release.gpu.global.u32 [%0], %1;"
                             :: "l"(myflag), "r"(v0 + (unsigned)T_) : "memory");
            }
        }
    }

    if (FUSE_FC) {
        // hb holds h_T for the group's 4 batches (full H).
        if (tid < 128) {
            int b = tid >> 5;
            int nl = tid & 31;
            int n = c * (O_ / CPG) + nl;
            const float4* hT = (const float4*)&hb[b][0];
            const float4* wf = (const float4*)(Wfc + (size_t)n * H_);
            float acc = 0.f;
#pragma unroll 8
            for (int k4 = 0; k4 < H_ / 4; k4++) {
                float4 a = wf[k4];
                float4 x = hT[k4];
                acc += a.x * x.x + a.y * x.y + a.z * x.z + a.w * x.w;
            }
            out[(g * BPG + b) * O_ + n] = acc + bfc[n];
        }
    }
}

// ---------------------------------------------------------------------------

extern "C" void kernel_launch(void* const* d_in, const int* in_sizes, int n_in,
                              void* d_out, int out_size)
{
    const float* x     = (const float*)d_in[0];
    const float* W_ih0 = (const float*)d_in[1];
    const float* W_hh0 = (const float*)d_in[2];
    const float* b_ih0 = (const float*)d_in[3];
    const float* b_hh0 = (const float*)d_in[4];
    const float* W_ih1 = (const float*)d_in[5];
    const float* W_hh1 = (const float*)d_in[6];
    const float* b_ih1 = (const float*)d_in[7];
    const float* b_hh1 = (const float*)d_in[8];
    const float* W_fc  = (const float*)d_in[9];
    const float* b_fc  = (const float*)d_in[10];
    float* out = (float*)d_out;

    void* p_xw = nullptr;
    void* p_seq = nullptr;
    cudaGetSymbolAddress(&p_xw, g_xw);
    cudaGetSymbolAddress(&p_seq, g_seq);

    const int MT = B_ * T_;  // 65536

    // Layer 0 input projection: g_xw = x @ W_ih0^T + b_ih0 + b_hh0
    gemm_tf32<<<dim3(H_ / 128, MT / 128), 256>>>(
        x, W_ih0, b_ih0, b_hh0, (float*)p_xw, MT, H_, D_);

    // Layer 0 scan -> g_seq
    scan_kernel<true, false><<<GROUPS * CPG, 256>>>(
        W_hh0, nullptr, nullptr, nullptr);

    // Layer 1 input projection: g_xw = g_seq @ W_ih1^T + b_ih1 + b_hh1
    gemm_tf32<<<dim3(H_ / 128, MT / 128), 256>>>(
        (const float*)p_seq, W_ih1, b_ih1, b_hh1, (float*)p_xw, MT, H_, H_);

    // Layer 1 scan + fused fc -> out
    scan_kernel<false, true><<<GROUPS * CPG, 256>>>(
        W_hh1, W_fc, b_fc, out);
}

// round 8
// speedup vs baseline: 2.1460x; 1.4601x over previous
#include <cuda_runtime.h>
#include <math.h>
#include <stdint.h>

#define B_ 64
#define T_ 1024
#define D_ 256
#define H_ 512
#define O_ 256

#define GROUPS 16
#define CPG 8              // CTAs per group (column split of H)
#define BPG (B_ / GROUPS)  // 4 batches per group
#define COLS (H_ / CPG)    // 64 output columns per CTA
#define QPB 22             // quads per (CTA, batch): 64 cols = 21*3 + 1
#define QPERB (CPG * QPB)  // 176 quads per batch per group
#define TOTQ (BPG * QPERB) // 704 quads per group per step

typedef unsigned long long ull;

// Scratch (static device allocations; runtime alloc is forbidden)
__device__ float    g_xw[(size_t)B_ * T_ * H_];   // 128 MB: xW0, later reused as xW1
__device__ float    g_seq[(size_t)B_ * T_ * H_];  // 128 MB: layer-0 outputs
// Exchange quads: {h[3j],h[3j+1],h[3j+2], seq}. 16B stores/loads are single-copy
// atomic, so data+validity travel in ONE access: no fences, no acquire/release.
__device__ uint4    g_hq[2][GROUPS][BPG][QPERB];
// Monotonic per-group seq base; advanced by T_ per scan launch -> stamps are
// globally unique across launches/graph replays (stale data can never match).
__device__ unsigned g_base[GROUPS];

// ---------------------------------------------------------------------------
// Packed fp32x2 helpers (exact fp32 math, 2 FMAs per instruction)
// ---------------------------------------------------------------------------
__device__ __forceinline__ ull ffma2(ull a, ull b, ull c) {
    ull d;
    asm("fma.rn.f32x2 %0, %1, %2, %3;" : "=l"(d) : "l"(a), "l"(b), "l"(c));
    return d;
}
__device__ __forceinline__ ull addf2(ull a, ull b) {
    ull d;
    asm("add.rn.f32x2 %0, %1, %2;" : "=l"(d) : "l"(a), "l"(b));
    return d;
}
__device__ __forceinline__ ull pk2(float x, float y) {
    ull r;
    asm("mov.b64 %0, {%1, %2};" : "=l"(r) : "f"(x), "f"(y));
    return r;
}
__device__ __forceinline__ float2 unpk(ull a) {
    float2 f;
    asm("mov.b64 {%0, %1}, %2;" : "=f"(f.x), "=f"(f.y) : "l"(a));
    return f;
}

// Poll load: forced re-read each iteration (memory clobber), L2-cached (.cg)
__device__ __forceinline__ uint4 ldpoll(const uint4* p) {
    uint4 v;
    asm volatile("ld.global.cg.v4.u32 {%0,%1,%2,%3}, [%4];"
                 : "=r"(v.x), "=r"(v.y), "=r"(v.z), "=r"(v.w) : "l"(p) : "memory");
    return v;
}

// ---------------------------------------------------------------------------
// tf32 tensor-core GEMM: C[M,N] = A[M,K] @ B[N,K]^T + bias1[N] + bias2[N]
// 128x128 tile, BK=32, 256 threads, warp tile 32x64 (m16n8k8). (unchanged)
// ---------------------------------------------------------------------------
__device__ __forceinline__ unsigned f2tf32(float f) {
    unsigned r;
    asm("cvt.rna.tf32.f32 %0, %1;" : "=r"(r) : "f"(f));
    return r;
}
__device__ __forceinline__ void mma_tf32(float* c, unsigned a0, unsigned a1,
                                         unsigned a2, unsigned a3,
                                         unsigned b0, unsigned b1) {
    asm volatile(
        "mma.sync.aligned.m16n8k8.row.col.f32.tf32.tf32.f32 "
        "{%0,%1,%2,%3}, {%4,%5,%6,%7}, {%8,%9}, {%0,%1,%2,%3};\n"
        : "+f"(c[0]), "+f"(c[1]), "+f"(c[2]), "+f"(c[3])
        : "r"(a0), "r"(a1), "r"(a2), "r"(a3), "r"(b0), "r"(b1));
}

__global__ void __launch_bounds__(256) gemm_tf32(
    const float* __restrict__ A, const float* __restrict__ Bm,
    const float* __restrict__ b1, const float* __restrict__ b2,
    float* __restrict__ C, int M, int N, int K)
{
    __shared__ unsigned Asm[128 * 36];
    __shared__ unsigned Bsm[128 * 36];

    const int m0 = blockIdx.y * 128;
    const int n0 = blockIdx.x * 128;
    const int tid = threadIdx.x;
    const int lane = tid & 31;
    const int wid = tid >> 5;
    const int wm = wid & 3;
    const int wn = wid >> 2;
    const int l4 = lane >> 2;
    const int lm = lane & 3;

    float acc[2][8][4];
#pragma unroll
    for (int i = 0; i < 2; i++)
#pragma unroll
        for (int j = 0; j < 8; j++)
#pragma unroll
            for (int k = 0; k < 4; k++) acc[i][j][k] = 0.f;

    for (int k0 = 0; k0 < K; k0 += 32) {
#pragma unroll
        for (int i = 0; i < 4; i++) {
            int qg = tid + 256 * i;
            int row = qg >> 3;
            int q = qg & 7;
            float4 va = *(const float4*)(A + (size_t)(m0 + row) * K + k0 + q * 4);
            unsigned* da = &Asm[row * 36 + q * 4];
            da[0] = f2tf32(va.x); da[1] = f2tf32(va.y);
            da[2] = f2tf32(va.z); da[3] = f2tf32(va.w);
            float4 vb = *(const float4*)(Bm + (size_t)(n0 + row) * K + k0 + q * 4);
            unsigned* db = &Bsm[row * 36 + q * 4];
            db[0] = f2tf32(vb.x); db[1] = f2tf32(vb.y);
            db[2] = f2tf32(vb.z); db[3] = f2tf32(vb.w);
        }
        __syncthreads();

#pragma unroll
        for (int ks = 0; ks < 4; ks++) {
            unsigned a[2][4];
#pragma unroll
            for (int mt = 0; mt < 2; mt++) {
                const unsigned* ap = &Asm[(wm * 32 + mt * 16 + l4) * 36 + ks * 8 + lm];
                a[mt][0] = ap[0];
                a[mt][1] = ap[8 * 36];
                a[mt][2] = ap[4];
                a[mt][3] = ap[8 * 36 + 4];
            }
#pragma unroll
            for (int nt = 0; nt < 8; nt++) {
                const unsigned* bp = &Bsm[(wn * 64 + nt * 8 + l4) * 36 + ks * 8 + lm];
                unsigned b0 = bp[0];
                unsigned b1v = bp[4];
                mma_tf32(acc[0][nt], a[0][0], a[0][1], a[0][2], a[0][3], b0, b1v);
                mma_tf32(acc[1][nt], a[1][0], a[1][1], a[1][2], a[1][3], b0, b1v);
            }
        }
        __syncthreads();
    }

#pragma unroll
    for (int nt = 0; nt < 8; nt++) {
        int n = n0 + wn * 64 + nt * 8 + 2 * lm;
        float bv0 = b1[n] + b2[n];
        float bv1 = b1[n + 1] + b2[n + 1];
#pragma unroll
        for (int mt = 0; mt < 2; mt++) {
            int r = m0 + wm * 32 + mt * 16 + l4;
            float2 v0 = make_float2(acc[mt][nt][0] + bv0, acc[mt][nt][1] + bv1);
            float2 v1 = make_float2(acc[mt][nt][2] + bv0, acc[mt][nt][3] + bv1);
            *(float2*)(C + (size_t)r * N + n) = v0;
            *(float2*)(C + (size_t)(r + 8) * N + n) = v1;
        }
    }
}

// ---------------------------------------------------------------------------
// Persistent recurrent scan: W in registers, seq-embedded quad exchange.
// Grid = 128 CTAs (1/SM, wave-1). CTA (g,c): batches [g*4,g*4+4),
// columns [c*64,c*64+64). Per step: FFMA2 GEMM from SMEM hb + reg W,
// emit h as {3 floats, seq} quads (one 16B atomic store), peers poll the
// quads directly (validity == data arrival; zero fences on the path).
// ---------------------------------------------------------------------------
template <bool STORE_SEQ, bool FUSE_FC>
__global__ void __launch_bounds__(256) scan_kernel(
    const float* __restrict__ Whh,
    const float* __restrict__ Wfc, const float* __restrict__ bfc,
    float* __restrict__ out)
{
    __shared__ __align__(16) float hb[BPG][H_];        // 8 KB: group hidden state
    __shared__ __align__(16) float part[4][BPG][COLS]; // 4 KB: k-partials
    __shared__ __align__(16) float stg[BPG][COLS];     // 1 KB: staged hn
    __shared__ unsigned sv0;

    const int tid = threadIdx.x;
    const int g = blockIdx.x >> 3;
    const int c = blockIdx.x & 7;

    const int c_loc = tid & 63;   // output column within slice
    const int kg    = tid >> 6;   // K-slice (4 x 128)
    const int ob    = tid >> 6;   // reduce mapping: batch
    const int oj    = tid & 63;   // reduce mapping: column
    const int bglob = g * BPG + ob;
    const int jglob = c * COLS + oj;

    // ---- W slice into registers (one-time; 16 CTAs share each slice via L2)
    ull w[64];
    {
        const float4* wp = (const float4*)(Whh + (size_t)(c * COLS + c_loc) * H_ + kg * 128);
#pragma unroll
        for (int i = 0; i < 32; i++) {
            float4 v = wp[i];
            w[2 * i]     = pk2(v.x, v.y);
            w[2 * i + 1] = pk2(v.z, v.w);
        }
    }

    if (tid == 0) sv0 = g_base[g];
    for (int i = tid; i < BPG * H_; i += 256) (&hb[0][0])[i] = 0.f;  // h0 = 0
    __syncthreads();
    const unsigned v0 = sv0;

    // ---- precomputed poll slots (fixed across steps): <=3 quads per thread
    int      pq_idx[3];
    float*   pq_hb[3];
    bool     pq_full[3];   // quad carries 3 valid cols (q != 21)
    bool     pq_on[3];
#pragma unroll
    for (int j = 0; j < 3; j++) {
        int idx = tid + 256 * j;
        pq_on[j] = (idx < TOTQ);
        int ii = pq_on[j] ? idx : 0;
        int b = ii / QPERB;
        int qq = ii % QPERB;
        int csrc = qq / QPB;
        int q = qq % QPB;
        pq_idx[j] = ii;
        pq_hb[j] = &hb[b][csrc * COLS + 3 * q];
        pq_full[j] = (q != QPB - 1);
    }
    const uint4* hq_base[2] = { &g_hq[0][g][0][0], &g_hq[1][g][0][0] };

    const float* xwp = g_xw + (size_t)bglob * T_ * H_ + jglob;

    for (int t = 0; t < T_; t++) {
        // stream this step's input projection early (hides DRAM latency)
        float xw_r = __ldcg(xwp + (size_t)t * H_);

        const ulonglong2* h0 = (const ulonglong2*)&hb[0][kg * 128];
        const ulonglong2* h1 = (const ulonglong2*)&hb[1][kg * 128];
        const ulonglong2* h2 = (const ulonglong2*)&hb[2][kg * 128];
        const ulonglong2* h3 = (const ulonglong2*)&hb[3][kg * 128];

        ull a0 = 0ull, b0 = 0ull, a1 = 0ull, b1 = 0ull;
        ull a2 = 0ull, b2 = 0ull, a3 = 0ull, b3 = 0ull;
#pragma unroll
        for (int q = 0; q < 32; q++) {
            ulonglong2 v0v = h0[q];   // broadcast LDS.128
            a0 = ffma2(w[2 * q], v0v.x, a0);
            b0 = ffma2(w[2 * q + 1], v0v.y, b0);
            ulonglong2 v1 = h1[q];
            a1 = ffma2(w[2 * q], v1.x, a1);
            b1 = ffma2(w[2 * q + 1], v1.y, b1);
            ulonglong2 v2 = h2[q];
            a2 = ffma2(w[2 * q], v2.x, a2);
            b2 = ffma2(w[2 * q + 1], v2.y, b2);
            ulonglong2 v3 = h3[q];
            a3 = ffma2(w[2 * q], v3.x, a3);
            b3 = ffma2(w[2 * q + 1], v3.y, b3);
        }
        float2 s0 = unpk(addf2(a0, b0));
        float2 s1 = unpk(addf2(a1, b1));
        float2 s2 = unpk(addf2(a2, b2));
        float2 s3 = unpk(addf2(a3, b3));
        part[kg][0][c_loc] = s0.x + s0.y;
        part[kg][1][c_loc] = s1.x + s1.y;
        part[kg][2][c_loc] = s2.x + s2.y;
        part[kg][3][c_loc] = s3.x + s3.y;
        __syncthreads();

        float s = part[0][ob][oj] + part[1][ob][oj] + part[2][ob][oj]
                + part[3][ob][oj] + xw_r;
        float hn = tanhf(s);

        if ((!FUSE_FC) && (t == T_ - 1)) {
            // last step, layer 0: nobody consumes h_T via exchange
            if (STORE_SEQ) __stcg(&g_seq[((size_t)bglob * T_ + t) * H_ + jglob], hn);
            break;
        }

        stg[ob][oj] = hn;
        __syncthreads();

        const int p = t & 1;
        const unsigned want = v0 + (unsigned)t + 1u;

        // ---- emit: 88 threads write this CTA's quads {3 h, seq}
        if (tid < BPG * QPB) {
            int b = tid / QPB;
            int q = tid % QPB;
            int cl = 3 * q;
            uint4 v;
            v.x = __float_as_uint(stg[b][cl]);
            v.y = __float_as_uint((cl + 1 < COLS) ? stg[b][cl + 1] : 0.f);
            v.z = __float_as_uint((cl + 2 < COLS) ? stg[b][cl + 2] : 0.f);
            v.w = want;
            __stcg((uint4*)&g_hq[p][g][b][c * QPB + q], v);
        }
        if (STORE_SEQ) __stcg(&g_seq[((size_t)bglob * T_ + t) * H_ + jglob], hn);

        // ---- poll peers' quads (data+validity in one 16B access) + unpack
        {
            const uint4* base = hq_base[p];
            uint4 r0, r1, r2;
            bool d0 = !pq_on[0], d1 = !pq_on[1], d2 = !pq_on[2];
            do {
                if (!d0) { r0 = ldpoll(base + pq_idx[0]); d0 = (r0.w == want); }
                if (!d1) { r1 = ldpoll(base + pq_idx[1]); d1 = (r1.w == want); }
                if (!d2) { r2 = ldpoll(base + pq_idx[2]); d2 = (r2.w == want); }
            } while (!(d0 && d1 && d2));
            if (pq_on[0]) {
                pq_hb[0][0] = __uint_as_float(r0.x);
                if (pq_full[0]) { pq_hb[0][1] = __uint_as_float(r0.y);
                                  pq_hb[0][2] = __uint_as_float(r0.z); }
            }
            if (pq_on[1]) {
                pq_hb[1][0] = __uint_as_float(r1.x);
                if (pq_full[1]) { pq_hb[1][1] = __uint_as_float(r1.y);
                                  pq_hb[1][2] = __uint_as_float(r1.z); }
            }
            if (pq_on[2]) {
                pq_hb[2][0] = __uint_as_float(r2.x);
                if (pq_full[2]) { pq_hb[2][1] = __uint_as_float(r2.y);
                                  pq_hb[2][2] = __uint_as_float(r2.z); }
            }
        }
        __syncthreads();
    }

    if (FUSE_FC) {
        // hb holds h_T for the group's 4 batches (full H).
        if (tid < 128) {
            int b = tid >> 5;
            int nl = tid & 31;
            int n = c * (O_ / CPG) + nl;
            const float4* hT = (const float4*)&hb[b][0];
            const float4* wf = (const float4*)(Wfc + (size_t)n * H_);
            float acc = 0.f;
#pragma unroll 8
            for (int k4 = 0; k4 < H_ / 4; k4++) {
                float4 a = wf[k4];
                float4 x = hT[k4];
                acc += a.x * x.x + a.y * x.y + a.z * x.z + a.w * x.w;
            }
            out[(g * BPG + b) * O_ + n] = acc + bfc[n];
        }
    }

    // advance the group's seq base for the next launch (monotonic, replay-safe)
    if (c == 0 && tid == 0) g_base[g] = v0 + (unsigned)T_;
}

// ---------------------------------------------------------------------------

extern "C" void kernel_launch(void* const* d_in, const int* in_sizes, int n_in,
                              void* d_out, int out_size)
{
    const float* x     = (const float*)d_in[0];
    const float* W_ih0 = (const float*)d_in[1];
    const float* W_hh0 = (const float*)d_in[2];
    const float* b_ih0 = (const float*)d_in[3];
    const float* b_hh0 = (const float*)d_in[4];
    const float* W_ih1 = (const float*)d_in[5];
    const float* W_hh1 = (const float*)d_in[6];
    const float* b_ih1 = (const float*)d_in[7];
    const float* b_hh1 = (const float*)d_in[8];
    const float* W_fc  = (const float*)d_in[9];
    const float* b_fc  = (const float*)d_in[10];
    float* out = (float*)d_out;

    void* p_xw = nullptr;
    void* p_seq = nullptr;
    cudaGetSymbolAddress(&p_xw, g_xw);
    cudaGetSymbolAddress(&p_seq, g_seq);

    const int MT = B_ * T_;  // 65536

    // Layer 0 input projection: g_xw = x @ W_ih0^T + b_ih0 + b_hh0
    gemm_tf32<<<dim3(H_ / 128, MT / 128), 256>>>(
        x, W_ih0, b_ih0, b_hh0, (float*)p_xw, MT, H_, D_);

    // Layer 0 scan -> g_seq
    scan_kernel<true, false><<<GROUPS * CPG, 256>>>(
        W_hh0, nullptr, nullptr, nullptr);

    // Layer 1 input projection: g_xw = g_seq @ W_ih1^T + b_ih1 + b_hh1
    gemm_tf32<<<dim3(H_ / 128, MT / 128), 256>>>(
        (const float*)p_seq, W_ih1, b_ih1, b_hh1, (float*)p_xw, MT, H_, H_);

    // Layer 1 scan + fused fc -> out
    scan_kernel<false, true><<<GROUPS * CPG, 256>>>(
        W_hh1, W_fc, b_fc, out);
}